// round 1
// baseline (speedup 1.0000x reference)
#include <cuda_runtime.h>
#include <cuda_bf16.h>

#define DN   512
#define NB   32
#define NR   131072
#define RK   16
#define TOPK 8

// ---------------- scratch (static device arrays; no allocs) ----------------
__device__ float g_qpart[NB * 4 * DN];
__device__ float g_qmean[NB * DN];
__device__ float g_qB[NB * RK];
__device__ float g_scores[(size_t)NR * NB];          // [n][b] layout, 16MB
__device__ unsigned long long g_cand[NB * 64 * TOPK];
__device__ int   g_topidx[NB * TOPK];
__device__ float g_xsum[NB * DN];
__device__ float g_gx[NB * 3 * DN];
__device__ float g_wp[NB];

__device__ __forceinline__ float sigmf(float x) { return 1.0f / (1.0f + expf(-x)); }

__device__ __forceinline__ unsigned ford(float f) {
    unsigned u = __float_as_uint(f);
    return (u & 0x80000000u) ? ~u : (u | 0x80000000u);
}

__device__ __forceinline__ void ffma2(unsigned long long &c, unsigned long long a, unsigned long long b) {
    asm("fma.rn.f32x2 %0, %1, %2, %0;" : "+l"(c) : "l"(a), "l"(b));
}

// ---------------- K0: partial sums of query over S ----------------
__global__ void k_qpart(const float* __restrict__ query) {
    int b = blockIdx.x, j = blockIdx.y, d = threadIdx.x;
    const float* p = query + (size_t)b * 128 * DN + (size_t)j * 32 * DN + d;
    float s = 0.f;
    #pragma unroll 8
    for (int i = 0; i < 32; ++i) s += p[i * DN];
    g_qpart[(b * 4 + j) * DN + d] = s;
}

// ---------------- K0b: qmean + qB = q @ lora_B^T ----------------
__global__ void k_qmean_qB(const float* __restrict__ loraB) {
    int b = blockIdx.x, d = threadIdx.x;
    float q = (g_qpart[(b * 4 + 0) * DN + d] + g_qpart[(b * 4 + 1) * DN + d] +
               g_qpart[(b * 4 + 2) * DN + d] + g_qpart[(b * 4 + 3) * DN + d]) * (1.0f / 128.0f);
    g_qmean[b * DN + d] = q;
    __shared__ float sq[DN];
    sq[d] = q;
    __syncthreads();
    int w = d >> 5, lane = d & 31;   // w = r (16 warps = 16 lora ranks)
    float p = 0.f;
    #pragma unroll
    for (int j = 0; j < 16; ++j) p += sq[lane + 32 * j] * loraB[w * DN + lane + 32 * j];
    #pragma unroll
    for (int o = 16; o > 0; o >>= 1) p += __shfl_xor_sync(0xFFFFFFFFu, p, o);
    if (lane == 0) g_qB[b * RK + w] = p;
}

// ---------------- K1: fused scores GEMM + base->new_mem copy ----------------
// block: 256 threads, 128 rows x 32 batches, thread tile 4x4, f32x2 FMA packed along K.
#define KC 64
__global__ __launch_bounds__(256, 2) void k_scores(
    const float* __restrict__ base, const float* __restrict__ loraA,
    float* __restrict__ out_mem) {
    __shared__ float tile[128][KC + 4];
    __shared__ float qsm[NB][KC + 4];
    const int row0 = blockIdx.x * 128;
    const int tid = threadIdx.x;
    const int bg = tid & 7, rg = tid >> 3;

    unsigned long long acc[4][4];
    #pragma unroll
    for (int r = 0; r < 4; ++r)
        #pragma unroll
        for (int b = 0; b < 4; ++b) acc[r][b] = 0ull;

    for (int kc = 0; kc < DN; kc += KC) {
        // stage base tile (and emit the new_mem copy for free)
        #pragma unroll
        for (int i = 0; i < 8; ++i) {
            int f = tid + i * 256;             // 2048 float4 per chunk
            int r = f >> 4, c4 = f & 15;
            size_t g = (size_t)(row0 + r) * DN + kc + c4 * 4;
            float4 v = *(const float4*)(base + g);
            *(float4*)(out_mem + g) = v;
            *(float4*)(&tile[r][c4 * 4]) = v;
        }
        // stage q chunk (row-major, so q pairs along K are contiguous)
        #pragma unroll
        for (int i = 0; i < 2; ++i) {
            int f = tid + i * 256;             // 512 float4
            int b = f >> 4, c4 = f & 15;
            *(float4*)(&qsm[b][c4 * 4]) = *(const float4*)(g_qmean + b * DN + kc + c4 * 4);
        }
        __syncthreads();

        #pragma unroll 4
        for (int d = 0; d < KC; d += 4) {
            ulonglong2 rv[4], qv[4];
            #pragma unroll
            for (int r = 0; r < 4; ++r) rv[r] = *(const ulonglong2*)(&tile[rg * 4 + r][d]);
            #pragma unroll
            for (int b = 0; b < 4; ++b) qv[b] = *(const ulonglong2*)(&qsm[bg * 4 + b][d]);
            #pragma unroll
            for (int r = 0; r < 4; ++r)
                #pragma unroll
                for (int b = 0; b < 4; ++b) {
                    ffma2(acc[r][b], rv[r].x, qv[b].x);
                    ffma2(acc[r][b], rv[r].y, qv[b].y);
                }
        }
        __syncthreads();
    }

    // epilogue: horizontal add + LoRA term, store scores [n][b] coalesced
    #pragma unroll
    for (int r = 0; r < 4; ++r) {
        int n = row0 + rg * 4 + r;
        float a_row[RK];
        #pragma unroll
        for (int i = 0; i < 4; ++i)
            *(float4*)&a_row[i * 4] = *(const float4*)(loraA + (size_t)n * RK + i * 4);
        float4 sv;
        float* sp = (float*)&sv;
        #pragma unroll
        for (int b = 0; b < 4; ++b) {
            int bb = bg * 4 + b;
            unsigned long long a = acc[r][b];
            float s = __uint_as_float((unsigned)(a & 0xFFFFFFFFull)) +
                      __uint_as_float((unsigned)(a >> 32));
            #pragma unroll
            for (int i = 0; i < RK; ++i) s += a_row[i] * g_qB[bb * RK + i];
            sp[b] = s;
        }
        *(float4*)(&g_scores[(size_t)n * NB + bg * 4]) = sv;
    }
}

// ---------------- K2a: per-range top-8 per batch ----------------
__global__ void k_topk_a() {
    const int tid = threadIdx.x;
    const int lane = tid & 31;        // batch
    const int w = tid >> 5;           // n-subrange within block
    const int n0 = blockIdx.x * 2048 + w * 256;

    unsigned long long top[TOPK];
    #pragma unroll
    for (int i = 0; i < TOPK; ++i) top[i] = 0ull;

    for (int j = 0; j < 256; ++j) {
        int n = n0 + j;
        float v = g_scores[(size_t)n * NB + lane];
        unsigned long long key = ((unsigned long long)ford(v) << 32) |
                                 (unsigned long long)(0xFFFFFFFFu - (unsigned)n);
        if (key > top[TOPK - 1]) {
            #pragma unroll
            for (int i = 0; i < TOPK; ++i) {
                if (key > top[i]) { unsigned long long t = top[i]; top[i] = key; key = t; }
            }
        }
    }

    __shared__ unsigned long long sk[8][NB][TOPK];
    #pragma unroll
    for (int i = 0; i < TOPK; ++i) sk[w][lane][i] = top[i];
    __syncthreads();

    if (w == 0) {  // lane = batch; merge the 8 subranges
        unsigned long long best[TOPK];
        #pragma unroll
        for (int i = 0; i < TOPK; ++i) best[i] = sk[0][lane][i];
        for (int g = 1; g < 8; ++g) {
            #pragma unroll
            for (int i = 0; i < TOPK; ++i) {
                unsigned long long key = sk[g][lane][i];
                if (key > best[TOPK - 1]) {
                    #pragma unroll
                    for (int q = 0; q < TOPK; ++q) {
                        if (key > best[q]) { unsigned long long t = best[q]; best[q] = key; key = t; }
                    }
                }
            }
        }
        #pragma unroll
        for (int i = 0; i < TOPK; ++i)
            g_cand[((size_t)lane * 64 + blockIdx.x) * TOPK + i] = best[i];
    }
}

// ---------------- K2b: final top-8 per batch (exact lax.top_k order) ----------------
__global__ void k_topk_b() {
    __shared__ unsigned long long keys[512];
    __shared__ unsigned long long red[128];
    int b = blockIdx.x, tid = threadIdx.x;
    for (int i = tid; i < 512; i += 128) keys[i] = g_cand[(size_t)b * 512 + i];
    __syncthreads();
    for (int k = 0; k < TOPK; ++k) {
        unsigned long long m = 0ull;
        for (int i = tid; i < 512; i += 128) m = max(m, keys[i]);
        red[tid] = m;
        __syncthreads();
        for (int o = 64; o > 0; o >>= 1) {
            if (tid < o) red[tid] = max(red[tid], red[tid + o]);
            __syncthreads();
        }
        unsigned long long M = red[0];
        __syncthreads();
        for (int i = tid; i < 512; i += 128) if (keys[i] == M) keys[i] = 0ull;
        if (tid == 0) g_topidx[b * TOPK + k] = (int)(0xFFFFFFFFu - (unsigned)(M & 0xFFFFFFFFull));
        __syncthreads();
    }
}

// ---------------- K3: retrieved = mem[idx] (with LoRA), xsum ----------------
__global__ void k_retrieve(const float* __restrict__ base,
                           const float* __restrict__ loraA,
                           const float* __restrict__ loraB,
                           float* __restrict__ out_retr) {
    int b = blockIdx.x, d = threadIdx.x;
    __shared__ float sa[TOPK][RK];
    __shared__ int sx[TOPK];
    if (d < TOPK) sx[d] = g_topidx[b * TOPK + d];
    __syncthreads();
    if (d < TOPK * RK) sa[d >> 4][d & 15] = loraA[(size_t)sx[d >> 4] * RK + (d & 15)];
    __syncthreads();
    float s = 0.f;
    #pragma unroll
    for (int k = 0; k < TOPK; ++k) {
        float v = base[(size_t)sx[k] * DN + d];
        #pragma unroll
        for (int r = 0; r < RK; ++r) v += sa[k][r] * loraB[r * DN + d];
        out_retr[((size_t)b * TOPK + k) * DN + d] = v;
        s += v;
    }
    g_xsum[b * DN + d] = s;
}

// ---------------- K3b: gx = xsum @ w_ih^T + b_ih ----------------
__global__ void k_gx(const float* __restrict__ w_ih, const float* __restrict__ b_ih) {
    int g = blockIdx.x, tid = threadIdx.x;
    int lane = tid & 31, w = tid >> 5;
    __shared__ float sw[DN];
    *(float4*)&sw[tid * 4] = *(const float4*)(w_ih + (size_t)g * DN + tid * 4);
    __syncthreads();
    for (int bb = 0; bb < 8; ++bb) {
        int b = w * 8 + bb;
        float p = 0.f;
        #pragma unroll
        for (int j = 0; j < 16; ++j)
            p += sw[lane + 32 * j] * g_xsum[b * DN + lane + 32 * j];
        #pragma unroll
        for (int o = 16; o > 0; o >>= 1) p += __shfl_xor_sync(0xFFFFFFFFu, p, o);
        if (lane == 0) g_gx[(size_t)b * 3 * DN + g] = p + b_ih[g];
    }
}

// ---------------- K3c: GRU (h0 = 0) + write gate ----------------
__global__ void k_hidden(const float* __restrict__ b_hh,
                         const float* __restrict__ wg_w, const float* __restrict__ wg_b,
                         float* __restrict__ out_hidden) {
    int b = blockIdx.x, d = threadIdx.x;
    const float* gx = g_gx + (size_t)b * 3 * DN;
    float r = sigmf(gx[d] + b_hh[d]);
    float z = sigmf(gx[DN + d] + b_hh[DN + d]);
    float n = tanhf(gx[2 * DN + d] + r * b_hh[2 * DN + d]);
    float h = (1.0f - z) * n;          // + z*h0, h0 = 0
    out_hidden[(size_t)b * DN + d] = h;
    __shared__ float red[DN];
    red[d] = h * wg_w[d];
    __syncthreads();
    for (int o = 256; o > 0; o >>= 1) {
        if (d < o) red[d] += red[d + o];
        __syncthreads();
    }
    if (d == 0) g_wp[b] = sigmf(red[0] + wg_b[0]);
}

// ---------------- K4: apply sequential-scan writes (last-writer replays chain) --------
__global__ void k_apply(const float* __restrict__ base, float* __restrict__ out_mem) {
    __shared__ int sidx[NB * TOPK];
    __shared__ float swp[NB];
    int tid = threadIdx.x;
    if (tid < NB * TOPK) sidx[tid] = g_topidx[tid];
    if (tid < NB) swp[tid] = g_wp[tid];
    __syncthreads();
    int p = blockIdx.x;
    int x = sidx[p];
    for (int p2 = p + 1; p2 < NB * TOPK; ++p2)
        if (sidx[p2] == x) return;     // a later batch rewrites this row
    float m = base[(size_t)x * DN + tid];
    for (int p2 = 0; p2 <= p; ++p2) {
        if (sidx[p2] == x) {
            float pw = swp[p2 >> 3];
            m = (1.0f - pw) * m + pw * g_qmean[(p2 >> 3) * DN + tid];
        }
    }
    out_mem[(size_t)x * DN + tid] = m;
}

// ---------------- launch ----------------
extern "C" void kernel_launch(void* const* d_in, const int* in_sizes, int n_in,
                              void* d_out, int out_size) {
    const float* query  = (const float*)d_in[0];
    const float* base   = (const float*)d_in[1];
    const float* loraA  = (const float*)d_in[2];
    const float* loraB  = (const float*)d_in[3];
    const float* w_ih   = (const float*)d_in[4];
    // d_in[5] = gru_w_hh: unused (h0 = 0 -> gh = b_hh exactly)
    const float* b_ih   = (const float*)d_in[6];
    const float* b_hh   = (const float*)d_in[7];
    const float* wg_w   = (const float*)d_in[8];
    const float* wg_b   = (const float*)d_in[9];

    float* out_retr   = (float*)d_out;                       // [32,8,512]
    float* out_hidden = out_retr + (size_t)NB * TOPK * DN;   // [32,512]
    float* out_mem    = out_hidden + (size_t)NB * DN;        // [131072,512]

    k_qpart<<<dim3(NB, 4), DN>>>(query);
    k_qmean_qB<<<NB, DN>>>(loraB);
    k_scores<<<NR / 128, 256>>>(base, loraA, out_mem);
    k_topk_a<<<64, 256>>>();
    k_topk_b<<<NB, 128>>>();
    k_retrieve<<<NB, DN>>>(base, loraA, loraB, out_retr);
    k_gx<<<3 * DN, 128>>>(w_ih, b_ih);
    k_hidden<<<NB, DN>>>(b_hh, wg_w, wg_b, out_hidden);
    k_apply<<<NB * TOPK, DN>>>(base, out_mem);
}

// round 3
// speedup vs baseline: 2.1268x; 2.1268x over previous
#include <cuda_runtime.h>
#include <cuda_bf16.h>

#define DN    512
#define NB    32
#define NR    131072
#define RK    16
#define TOPK  8
#define MROWS 256
#define KC    32
#define NBLK  (NR / MROWS)   // 512 blocks

// ---------------- scratch (static device arrays; no allocs) ----------------
__device__ __align__(16) float g_qpart[NB * 4 * DN];
__device__ __align__(16) float g_qmean[NB * DN];
__device__ __align__(16) float g_qB[NB * RK];
__device__ unsigned long long g_cand[(size_t)NB * NBLK * TOPK];   // 1MB
__device__ int   g_topidx[NB * TOPK];
__device__ __align__(16) float g_xsum[NB * DN];
__device__ float g_gx[NB * 3 * DN];
__device__ float g_wp[NB];

__device__ __forceinline__ float sigmf(float x) { return 1.0f / (1.0f + expf(-x)); }

__device__ __forceinline__ unsigned ford(float f) {
    unsigned u = __float_as_uint(f);
    return (u & 0x80000000u) ? ~u : (u | 0x80000000u);
}

__device__ __forceinline__ void ffma2(unsigned long long &c, unsigned long long a, unsigned long long b) {
    asm("fma.rn.f32x2 %0, %1, %2, %0;" : "+l"(c) : "l"(a), "l"(b));
}

// descending top-8 insertion
__device__ __forceinline__ void ins8(unsigned long long (&top)[TOPK], unsigned long long key) {
    if (key > top[TOPK - 1]) {
        #pragma unroll
        for (int i = 0; i < TOPK; ++i)
            if (key > top[i]) { unsigned long long t = top[i]; top[i] = key; key = t; }
    }
}

// ---------------- K0: partial sums of query over S ----------------
__global__ void k_qpart(const float* __restrict__ query) {
    int b = blockIdx.x, j = blockIdx.y, d = threadIdx.x;
    const float* p = query + (size_t)b * 128 * DN + (size_t)j * 32 * DN + d;
    float s = 0.f;
    #pragma unroll 8
    for (int i = 0; i < 32; ++i) s += p[i * DN];
    g_qpart[(b * 4 + j) * DN + d] = s;
}

// ---------------- K0b: qmean + qB = q @ lora_B^T ----------------
__global__ void k_qmean_qB(const float* __restrict__ loraB) {
    int b = blockIdx.x, d = threadIdx.x;
    float q = (g_qpart[(b * 4 + 0) * DN + d] + g_qpart[(b * 4 + 1) * DN + d] +
               g_qpart[(b * 4 + 2) * DN + d] + g_qpart[(b * 4 + 3) * DN + d]) * (1.0f / 128.0f);
    g_qmean[b * DN + d] = q;
    __shared__ float sq[DN];
    sq[d] = q;
    __syncthreads();
    int w = d >> 5, lane = d & 31;   // w = r (16 warps = 16 lora ranks)
    float p = 0.f;
    #pragma unroll
    for (int j = 0; j < 16; ++j) p += sq[lane + 32 * j] * loraB[w * DN + lane + 32 * j];
    #pragma unroll
    for (int o = 16; o > 0; o >>= 1) p += __shfl_xor_sync(0xFFFFFFFFu, p, o);
    if (lane == 0) g_qB[b * RK + w] = p;
}

// ---------------- K1: fused scores GEMM + copy + per-block top-8 ----------------
// 128 threads, tile 256 rows x 32 batches, thread tile 8x8, f32x2 FMA, XOR-swizzled smem.
__global__ __launch_bounds__(128) void k_scores(
    const float* __restrict__ base, const float* __restrict__ loraA,
    float* __restrict__ out_mem) {
    __shared__ float tile[MROWS * KC];                 // 32KB (swizzled)
    __shared__ float qsm[NB * KC];                     // 4KB  (swizzled)
    __shared__ float qBs[NB * RK];                     // 2KB
    __shared__ unsigned long long cand_sm[4][NB][TOPK];// 8KB

    const int tid = threadIdx.x;
    const int row0 = blockIdx.x * MROWS;
    const int rg = tid >> 2;       // 0..31, row group (8 rows)
    const int bg = tid & 3;        // 0..3,  batch group (8 batches)

    for (int i = tid; i < NB * RK; i += 128) qBs[i] = g_qB[i];

    unsigned long long acc[8][8];
    #pragma unroll
    for (int r = 0; r < 8; ++r)
        #pragma unroll
        for (int b = 0; b < 8; ++b) acc[r][b] = 0ull;

    for (int kc = 0; kc < DN; kc += KC) {
        // stage base tile (+ emit new_mem copy for free). 2048 float4.
        #pragma unroll
        for (int i = 0; i < 16; ++i) {
            int f = tid + i * 128;
            int r = f >> 3, c4 = f & 7;
            size_t g = (size_t)(row0 + r) * DN + kc + c4 * 4;
            float4 v = *(const float4*)(base + g);
            *(float4*)(out_mem + g) = v;
            int sw = (c4 ^ ((r >> 3) & 7)) << 2;
            *(float4*)(&tile[r * KC + sw]) = v;
        }
        // stage q chunk. 256 float4.
        #pragma unroll
        for (int i = 0; i < 2; ++i) {
            int f = tid + i * 128;
            int r = f >> 3, c4 = f & 7;
            float4 v = *(const float4*)(g_qmean + r * DN + kc + c4 * 4);
            int sw = (c4 ^ ((r >> 3) & 3)) << 2;
            *(float4*)(&qsm[r * KC + sw]) = v;
        }
        __syncthreads();

        #pragma unroll 4
        for (int d4 = 0; d4 < KC / 4; ++d4) {
            ulonglong2 qv[8];
            #pragma unroll
            for (int b = 0; b < 8; ++b) {
                int qr = bg * 8 + b;
                int sw = (d4 ^ (bg & 3)) << 2;
                qv[b] = *(const ulonglong2*)(&qsm[qr * KC + sw]);
            }
            #pragma unroll
            for (int r = 0; r < 8; ++r) {
                int row = rg * 8 + r;
                int sw = (d4 ^ (rg & 7)) << 2;
                ulonglong2 rv = *(const ulonglong2*)(&tile[row * KC + sw]);
                #pragma unroll
                for (int b = 0; b < 8; ++b) {
                    ffma2(acc[r][b], rv.x, qv[b].x);
                    ffma2(acc[r][b], rv.y, qv[b].y);
                }
            }
        }
        __syncthreads();
    }

    // epilogue: finish scores (+LoRA), drop into smem [256][32]
    float* scr = tile;
    #pragma unroll
    for (int r = 0; r < 8; ++r) {
        int nl = rg * 8 + r;
        int n = row0 + nl;
        float ar[RK];
        #pragma unroll
        for (int i = 0; i < 4; ++i)
            *(float4*)&ar[i * 4] = *(const float4*)(loraA + (size_t)n * RK + i * 4);
        #pragma unroll
        for (int b = 0; b < 8; ++b) {
            int bb = bg * 8 + b;
            unsigned long long a = acc[r][b];
            float s = __uint_as_float((unsigned)(a & 0xFFFFFFFFull)) +
                      __uint_as_float((unsigned)(a >> 32));
            #pragma unroll
            for (int i = 0; i < RK; ++i) s += ar[i] * qBs[bb * RK + i];
            scr[nl * NB + bb] = s;
        }
    }
    __syncthreads();

    // per-block top-8 per batch: thread t scans 64 rows for batch t&31
    {
        int batch = tid & 31, seg = tid >> 5;
        unsigned long long top[TOPK];
        #pragma unroll
        for (int i = 0; i < TOPK; ++i) top[i] = 0ull;
        #pragma unroll 4
        for (int j = 0; j < 64; ++j) {
            int nl = seg * 64 + j;
            float v = scr[nl * NB + batch];
            unsigned long long key = ((unsigned long long)ford(v) << 32) |
                                     (unsigned long long)(0xFFFFFFFFu - (unsigned)(row0 + nl));
            ins8(top, key);
        }
        #pragma unroll
        for (int i = 0; i < TOPK; ++i) cand_sm[seg][batch][i] = top[i];
    }
    __syncthreads();

    if (tid < NB) {
        unsigned long long best[TOPK];
        #pragma unroll
        for (int i = 0; i < TOPK; ++i) best[i] = cand_sm[0][tid][i];
        #pragma unroll
        for (int s = 1; s < 4; ++s)
            #pragma unroll
            for (int i = 0; i < TOPK; ++i) {
                unsigned long long key = cand_sm[s][tid][i];
                if (key <= best[TOPK - 1]) break;   // lists sorted descending
                ins8(best, key);
            }
        #pragma unroll
        for (int i = 0; i < TOPK; ++i)
            g_cand[((size_t)tid * NBLK + blockIdx.x) * TOPK + i] = best[i];
    }
}

// ---------------- K2: merge 4096 candidates per batch -> top-8 ----------------
__global__ void k_topk_merge() {
    __shared__ unsigned long long L[256][TOPK];
    __shared__ unsigned long long L2[32][TOPK];
    int b = blockIdx.x, t = threadIdx.x;
    const unsigned long long* src = g_cand + (size_t)b * NBLK * TOPK;   // 4096 keys

    unsigned long long top[TOPK];
    #pragma unroll
    for (int i = 0; i < TOPK; ++i) top[i] = 0ull;
    #pragma unroll 4
    for (int j = 0; j < 16; ++j) ins8(top, src[t * 16 + j]);
    #pragma unroll
    for (int i = 0; i < TOPK; ++i) L[t][i] = top[i];
    __syncthreads();

    if (t < 32) {
        unsigned long long best[TOPK];
        #pragma unroll
        for (int i = 0; i < TOPK; ++i) best[i] = L[t * 8][i];
        for (int l = 1; l < 8; ++l)
            #pragma unroll
            for (int i = 0; i < TOPK; ++i) {
                unsigned long long key = L[t * 8 + l][i];
                if (key <= best[TOPK - 1]) break;
                ins8(best, key);
            }
        #pragma unroll
        for (int i = 0; i < TOPK; ++i) L2[t][i] = best[i];
    }
    __syncthreads();

    if (t == 0) {
        unsigned long long best[TOPK];
        #pragma unroll
        for (int i = 0; i < TOPK; ++i) best[i] = L2[0][i];
        for (int l = 1; l < 32; ++l)
            #pragma unroll
            for (int i = 0; i < TOPK; ++i) {
                unsigned long long key = L2[l][i];
                if (key <= best[TOPK - 1]) break;
                ins8(best, key);
            }
        #pragma unroll
        for (int k = 0; k < TOPK; ++k)
            g_topidx[b * TOPK + k] = (int)(0xFFFFFFFFu - (unsigned)(best[k] & 0xFFFFFFFFull));
    }
}

// ---------------- K3: retrieved = mem[idx] (with LoRA), xsum ----------------
__global__ void k_retrieve(const float* __restrict__ base,
                           const float* __restrict__ loraA,
                           const float* __restrict__ loraB,
                           float* __restrict__ out_retr) {
    int b = blockIdx.x, d = threadIdx.x;
    __shared__ float sa[TOPK][RK];
    __shared__ int sx[TOPK];
    if (d < TOPK) sx[d] = g_topidx[b * TOPK + d];
    __syncthreads();
    if (d < TOPK * RK) sa[d >> 4][d & 15] = loraA[(size_t)sx[d >> 4] * RK + (d & 15)];
    __syncthreads();
    float s = 0.f;
    #pragma unroll
    for (int k = 0; k < TOPK; ++k) {
        float v = base[(size_t)sx[k] * DN + d];
        #pragma unroll
        for (int r = 0; r < RK; ++r) v += sa[k][r] * loraB[r * DN + d];
        out_retr[((size_t)b * TOPK + k) * DN + d] = v;
        s += v;
    }
    g_xsum[b * DN + d] = s;
}

// ---------------- K3b: gx = xsum @ w_ih^T + b_ih ----------------
__global__ void k_gx(const float* __restrict__ w_ih, const float* __restrict__ b_ih) {
    int g = blockIdx.x, tid = threadIdx.x;
    int lane = tid & 31, w = tid >> 5;
    __shared__ float sw[DN];
    *(float4*)&sw[tid * 4] = *(const float4*)(w_ih + (size_t)g * DN + tid * 4);
    __syncthreads();
    for (int bb = 0; bb < 8; ++bb) {
        int b = w * 8 + bb;
        float p = 0.f;
        #pragma unroll
        for (int j = 0; j < 16; ++j)
            p += sw[lane + 32 * j] * g_xsum[b * DN + lane + 32 * j];
        #pragma unroll
        for (int o = 16; o > 0; o >>= 1) p += __shfl_xor_sync(0xFFFFFFFFu, p, o);
        if (lane == 0) g_gx[(size_t)b * 3 * DN + g] = p + b_ih[g];
    }
}

// ---------------- K3c: GRU (h0 = 0) + write gate ----------------
__global__ void k_hidden(const float* __restrict__ b_hh,
                         const float* __restrict__ wg_w, const float* __restrict__ wg_b,
                         float* __restrict__ out_hidden) {
    int b = blockIdx.x, d = threadIdx.x;
    const float* gx = g_gx + (size_t)b * 3 * DN;
    float r = sigmf(gx[d] + b_hh[d]);
    float z = sigmf(gx[DN + d] + b_hh[DN + d]);
    float n = tanhf(gx[2 * DN + d] + r * b_hh[2 * DN + d]);
    float h = (1.0f - z) * n;          // + z*h0, h0 = 0
    out_hidden[(size_t)b * DN + d] = h;
    __shared__ float red[DN];
    red[d] = h * wg_w[d];
    __syncthreads();
    for (int o = 256; o > 0; o >>= 1) {
        if (d < o) red[d] += red[d + o];
        __syncthreads();
    }
    if (d == 0) g_wp[b] = sigmf(red[0] + wg_b[0]);
}

// ---------------- K4: apply sequential-scan writes (last-writer replays chain) --------
__global__ void k_apply(const float* __restrict__ base, float* __restrict__ out_mem) {
    __shared__ int sidx[NB * TOPK];
    __shared__ float swp[NB];
    int tid = threadIdx.x;
    if (tid < NB * TOPK) sidx[tid] = g_topidx[tid];
    if (tid < NB) swp[tid] = g_wp[tid];
    __syncthreads();
    int p = blockIdx.x;
    int x = sidx[p];
    for (int p2 = p + 1; p2 < NB * TOPK; ++p2)
        if (sidx[p2] == x) return;     // a later batch rewrites this row
    float m = base[(size_t)x * DN + tid];
    for (int p2 = 0; p2 <= p; ++p2) {
        if (sidx[p2] == x) {
            float pw = swp[p2 >> 3];
            m = (1.0f - pw) * m + pw * g_qmean[(p2 >> 3) * DN + tid];
        }
    }
    out_mem[(size_t)x * DN + tid] = m;
}

// ---------------- launch ----------------
extern "C" void kernel_launch(void* const* d_in, const int* in_sizes, int n_in,
                              void* d_out, int out_size) {
    const float* query  = (const float*)d_in[0];
    const float* base   = (const float*)d_in[1];
    const float* loraA  = (const float*)d_in[2];
    const float* loraB  = (const float*)d_in[3];
    const float* w_ih   = (const float*)d_in[4];
    // d_in[5] = gru_w_hh: unused (h0 = 0 -> gh = b_hh exactly)
    const float* b_ih   = (const float*)d_in[6];
    const float* b_hh   = (const float*)d_in[7];
    const float* wg_w   = (const float*)d_in[8];
    const float* wg_b   = (const float*)d_in[9];

    float* out_retr   = (float*)d_out;                       // [32,8,512]
    float* out_hidden = out_retr + (size_t)NB * TOPK * DN;   // [32,512]
    float* out_mem    = out_hidden + (size_t)NB * DN;        // [131072,512]

    k_qpart<<<dim3(NB, 4), DN>>>(query);
    k_qmean_qB<<<NB, DN>>>(loraB);
    k_scores<<<NBLK, 128>>>(base, loraA, out_mem);
    k_topk_merge<<<NB, 256>>>();
    k_retrieve<<<NB, DN>>>(base, loraA, loraB, out_retr);
    k_gx<<<3 * DN, 128>>>(w_ih, b_ih);
    k_hidden<<<NB, DN>>>(b_hh, wg_w, wg_b, out_hidden);
    k_apply<<<NB * TOPK, DN>>>(base, out_mem);
}

// round 6
// speedup vs baseline: 2.2144x; 1.0412x over previous
#include <cuda_runtime.h>
#include <cuda_bf16.h>

#define DN    512
#define NB    32
#define NR    131072
#define RK    16
#define TOPK  8
#define MROWS 256
#define KC    32
#define NBLK  (NR / MROWS)      // 512 blocks
#define NCHUNK (DN / KC)        // 16

// ---------------- scratch (static device arrays; no allocs) ----------------
__device__ __align__(16) float g_qmean[NB * DN];
__device__ __align__(16) float g_qB[NB * RK];
__device__ unsigned long long g_cand[(size_t)NB * NBLK * TOPK];   // 1MB
__device__ int   g_topidx[NB * TOPK];
__device__ __align__(16) float g_xsum[NB * DN];
__device__ float g_gx[NB * 3 * DN];
__device__ float g_wp[NB];

__device__ __forceinline__ float sigmf(float x) { return 1.0f / (1.0f + expf(-x)); }

__device__ __forceinline__ unsigned ford(float f) {
    unsigned u = __float_as_uint(f);
    return (u & 0x80000000u) ? ~u : (u | 0x80000000u);
}

__device__ __forceinline__ void ffma2(unsigned long long &c, unsigned long long a, unsigned long long b) {
    asm("fma.rn.f32x2 %0, %1, %2, %0;" : "+l"(c) : "l"(a), "l"(b));
}

__device__ __forceinline__ void cpa16(unsigned s, const void* g) {
    asm volatile("cp.async.cg.shared.global [%0], [%1], 16;" :: "r"(s), "l"(g));
}

// descending top-8 insertion
__device__ __forceinline__ void ins8(unsigned long long (&top)[TOPK], unsigned long long key) {
    if (key > top[TOPK - 1]) {
        #pragma unroll
        for (int i = 0; i < TOPK; ++i)
            if (key > top[i]) { unsigned long long t = top[i]; top[i] = key; key = t; }
    }
}

// ---------------- K0: fused qmean + qB = q @ lora_B^T ----------------
__global__ void k_qmean(const float* __restrict__ query, const float* __restrict__ loraB) {
    int b = blockIdx.x, d = threadIdx.x;               // 512 threads
    const float* p = query + (size_t)b * 128 * DN + d;
    float s = 0.f;
    #pragma unroll 8
    for (int i = 0; i < 128; ++i) s += p[i * DN];
    float q = s * (1.0f / 128.0f);
    g_qmean[b * DN + d] = q;
    __shared__ float sq[DN];
    sq[d] = q;
    __syncthreads();
    int w = d >> 5, lane = d & 31;                     // 16 warps = 16 lora ranks
    float pp = 0.f;
    #pragma unroll
    for (int j = 0; j < 16; ++j) pp += sq[lane + 32 * j] * loraB[w * DN + lane + 32 * j];
    #pragma unroll
    for (int o = 16; o > 0; o >>= 1) pp += __shfl_xor_sync(0xFFFFFFFFu, pp, o);
    if (lane == 0) g_qB[b * RK + w] = pp;
}

// ---------------- K1: fused scores GEMM + copy + per-block top-8 ----------------
// 128 threads, tile 256 rows x 32 batches, thread tile 8x8, f32x2 FMA,
// cp.async double-buffered pipeline, XOR-swizzled smem.
// dynamic smem layout (floats):
//   [0      : 8192 )  tile buf0        (also reused as score scratch [256][32])
//   [8192   : 16384)  tile buf1
//   [16384  : 17408)  q buf0
//   [17408  : 18432)  q buf1
//   [18432  : 18944)  qBs
//   [18944  : 20992)  cand (1024 ull)
#define SC_SMEM_FLOATS 20992
__global__ __launch_bounds__(128) void k_scores(
    const float* __restrict__ base, const float* __restrict__ loraA,
    float* __restrict__ out_mem) {
    extern __shared__ float sm[];
    float* qBs = sm + 18432;
    unsigned long long (*cand_sm)[NB][TOPK] =
        (unsigned long long (*)[NB][TOPK])(sm + 18944);

    const int tid = threadIdx.x;
    const int row0 = blockIdx.x * MROWS;
    const int rg = tid >> 2;       // 0..31 row group (8 rows)
    const int bg = tid & 3;        // 0..3  batch group (8 batches)

    for (int i = tid; i < NB * RK; i += 128) qBs[i] = g_qB[i];

    unsigned long long acc[8][8];
    #pragma unroll
    for (int r = 0; r < 8; ++r)
        #pragma unroll
        for (int b = 0; b < 8; ++b) acc[r][b] = 0ull;

    const unsigned smb = (unsigned)__cvta_generic_to_shared(sm);

    auto issue = [&](int kc, int buf) {
        unsigned tb = smb + (buf ? 8192u * 4u : 0u);
        unsigned qb = smb + 16384u * 4u + (buf ? 1024u * 4u : 0u);
        #pragma unroll
        for (int i = 0; i < 16; ++i) {
            int f = tid + i * 128;
            int r = f >> 3, c4 = f & 7;
            const float* g = base + (size_t)(row0 + r) * DN + kc + c4 * 4;
            int sw = (c4 ^ ((r >> 3) & 7)) << 2;
            cpa16(tb + (unsigned)(r * KC + sw) * 4u, g);
        }
        #pragma unroll
        for (int i = 0; i < 2; ++i) {
            int f = tid + i * 128;
            int r = f >> 3, c4 = f & 7;
            const float* g = g_qmean + r * DN + kc + c4 * 4;
            int sw = (c4 ^ ((r >> 3) & 3)) << 2;
            cpa16(qb + (unsigned)(r * KC + sw) * 4u, g);
        }
        asm volatile("cp.async.commit_group;" ::: "memory");
    };

    issue(0, 0);

    for (int c = 0; c < NCHUNK; ++c) {
        const int kc = c * KC;
        const int buf = c & 1;
        if (c + 1 < NCHUNK) {
            issue(kc + KC, buf ^ 1);
            asm volatile("cp.async.wait_group 1;" ::: "memory");
        } else {
            asm volatile("cp.async.wait_group 0;" ::: "memory");
        }
        __syncthreads();

        float* tile = sm + (buf ? 8192 : 0);
        float* qsm  = sm + 16384 + (buf ? 1024 : 0);

        // copy-out this chunk (smem -> out_mem), overlapped with next chunk's DMA
        #pragma unroll
        for (int i = 0; i < 16; ++i) {
            int f = tid + i * 128;
            int r = f >> 3, c4 = f & 7;
            int sw = (c4 ^ ((r >> 3) & 7)) << 2;
            float4 v = *(const float4*)(tile + r * KC + sw);
            *(float4*)(out_mem + (size_t)(row0 + r) * DN + kc + c4 * 4) = v;
        }

        #pragma unroll 4
        for (int d4 = 0; d4 < KC / 4; ++d4) {
            ulonglong2 qv[8];
            #pragma unroll
            for (int b = 0; b < 8; ++b) {
                int qr = bg * 8 + b;
                int sw = (d4 ^ (bg & 3)) << 2;
                qv[b] = *(const ulonglong2*)(qsm + qr * KC + sw);
            }
            #pragma unroll
            for (int r = 0; r < 8; ++r) {
                int row = rg * 8 + r;
                int sw = (d4 ^ (rg & 7)) << 2;
                ulonglong2 rv = *(const ulonglong2*)(tile + row * KC + sw);
                #pragma unroll
                for (int b = 0; b < 8; ++b) {
                    ffma2(acc[r][b], rv.x, qv[b].x);
                    ffma2(acc[r][b], rv.y, qv[b].y);
                }
            }
        }
        __syncthreads();
    }

    // epilogue: finish scores (+LoRA), drop into smem scratch [256][32] (tile buf0)
    float* scr = sm;
    #pragma unroll
    for (int r = 0; r < 8; ++r) {
        int nl = rg * 8 + r;
        int n = row0 + nl;
        float ar[RK];
        #pragma unroll
        for (int i = 0; i < 4; ++i)
            *(float4*)&ar[i * 4] = *(const float4*)(loraA + (size_t)n * RK + i * 4);
        #pragma unroll
        for (int b = 0; b < 8; ++b) {
            int bb = bg * 8 + b;
            unsigned long long a = acc[r][b];
            float s = __uint_as_float((unsigned)(a & 0xFFFFFFFFull)) +
                      __uint_as_float((unsigned)(a >> 32));
            #pragma unroll
            for (int i = 0; i < RK; ++i) s += ar[i] * qBs[bb * RK + i];
            scr[nl * NB + bb] = s;
        }
    }
    __syncthreads();

    // per-block top-8 per batch: thread t scans 64 rows for batch t&31
    {
        int batch = tid & 31, seg = tid >> 5;
        unsigned long long top[TOPK];
        #pragma unroll
        for (int i = 0; i < TOPK; ++i) top[i] = 0ull;
        #pragma unroll 4
        for (int j = 0; j < 64; ++j) {
            int nl = seg * 64 + j;
            float v = scr[nl * NB + batch];
            unsigned long long key = ((unsigned long long)ford(v) << 32) |
                                     (unsigned long long)(0xFFFFFFFFu - (unsigned)(row0 + nl));
            ins8(top, key);
        }
        #pragma unroll
        for (int i = 0; i < TOPK; ++i) cand_sm[seg][batch][i] = top[i];
    }
    __syncthreads();

    if (tid < NB) {
        unsigned long long best[TOPK];
        #pragma unroll
        for (int i = 0; i < TOPK; ++i) best[i] = cand_sm[0][tid][i];
        #pragma unroll
        for (int s = 1; s < 4; ++s)
            #pragma unroll
            for (int i = 0; i < TOPK; ++i) {
                unsigned long long key = cand_sm[s][tid][i];
                if (key <= best[TOPK - 1]) break;   // lists sorted descending
                ins8(best, key);
            }
        #pragma unroll
        for (int i = 0; i < TOPK; ++i)
            g_cand[((size_t)tid * NBLK + blockIdx.x) * TOPK + i] = best[i];
    }
}

// ---------------- K2: merge 4096 candidates per batch -> top-8 (log-depth) ----------------
__global__ void k_topk_merge() {
    __shared__ unsigned long long L[256][TOPK + 1];   // padded vs bank conflicts
    int b = blockIdx.x, t = threadIdx.x;
    const unsigned long long* src = g_cand + (size_t)b * NBLK * TOPK + (size_t)t * 16;

    unsigned long long top[TOPK];
    #pragma unroll
    for (int i = 0; i < TOPK; ++i) top[i] = 0ull;
    #pragma unroll
    for (int j = 0; j < 16; ++j) ins8(top, src[j]);
    #pragma unroll
    for (int i = 0; i < TOPK; ++i) L[t][i] = top[i];

    #pragma unroll
    for (int step = 128; step >= 1; step >>= 1) {
        __syncthreads();
        if (t < step) {
            #pragma unroll
            for (int i = 0; i < TOPK; ++i) {
                unsigned long long key = L[t + step][i];
                if (key <= top[TOPK - 1]) break;    // lists sorted descending
                ins8(top, key);
            }
            #pragma unroll
            for (int i = 0; i < TOPK; ++i) L[t][i] = top[i];
        }
    }
    if (t == 0) {
        #pragma unroll
        for (int k = 0; k < TOPK; ++k)
            g_topidx[b * TOPK + k] = (int)(0xFFFFFFFFu - (unsigned)(top[k] & 0xFFFFFFFFull));
    }
}

// ---------------- K3: retrieved = mem[idx] (with LoRA), xsum ----------------
__global__ void k_retrieve(const float* __restrict__ base,
                           const float* __restrict__ loraA,
                           const float* __restrict__ loraB,
                           float* __restrict__ out_retr) {
    int b = blockIdx.x, d = threadIdx.x;
    __shared__ float sa[TOPK][RK];
    __shared__ int sx[TOPK];
    if (d < TOPK) sx[d] = g_topidx[b * TOPK + d];
    __syncthreads();
    if (d < TOPK * RK) sa[d >> 4][d & 15] = loraA[(size_t)sx[d >> 4] * RK + (d & 15)];
    __syncthreads();
    float s = 0.f;
    #pragma unroll
    for (int k = 0; k < TOPK; ++k) {
        float v = base[(size_t)sx[k] * DN + d];
        #pragma unroll
        for (int r = 0; r < RK; ++r) v += sa[k][r] * loraB[r * DN + d];
        out_retr[((size_t)b * TOPK + k) * DN + d] = v;
        s += v;
    }
    g_xsum[b * DN + d] = s;
}

// ---------------- K3b: gx = xsum @ w_ih^T + b_ih ----------------
__global__ void k_gx(const float* __restrict__ w_ih, const float* __restrict__ b_ih) {
    int g = blockIdx.x, tid = threadIdx.x;
    int lane = tid & 31, w = tid >> 5;
    __shared__ float sw[DN];
    *(float4*)&sw[tid * 4] = *(const float4*)(w_ih + (size_t)g * DN + tid * 4);
    __syncthreads();
    for (int bb = 0; bb < 8; ++bb) {
        int b = w * 8 + bb;
        float p = 0.f;
        #pragma unroll
        for (int j = 0; j < 16; ++j)
            p += sw[lane + 32 * j] * g_xsum[b * DN + lane + 32 * j];
        #pragma unroll
        for (int o = 16; o > 0; o >>= 1) p += __shfl_xor_sync(0xFFFFFFFFu, p, o);
        if (lane == 0) g_gx[(size_t)b * 3 * DN + g] = p + b_ih[g];
    }
}

// ---------------- K3c: GRU (h0 = 0) + write gate ----------------
__global__ void k_hidden(const float* __restrict__ b_hh,
                         const float* __restrict__ wg_w, const float* __restrict__ wg_b,
                         float* __restrict__ out_hidden) {
    int b = blockIdx.x, d = threadIdx.x;
    const float* gx = g_gx + (size_t)b * 3 * DN;
    float r = sigmf(gx[d] + b_hh[d]);
    float z = sigmf(gx[DN + d] + b_hh[DN + d]);
    float n = tanhf(gx[2 * DN + d] + r * b_hh[2 * DN + d]);
    float h = (1.0f - z) * n;          // + z*h0, h0 = 0
    out_hidden[(size_t)b * DN + d] = h;
    __shared__ float red[DN];
    red[d] = h * wg_w[d];
    __syncthreads();
    for (int o = 256; o > 0; o >>= 1) {
        if (d < o) red[d] += red[d + o];
        __syncthreads();
    }
    if (d == 0) g_wp[b] = sigmf(red[0] + wg_b[0]);
}

// ---------------- K4: apply sequential-scan writes (last-writer replays chain) --------
__global__ void k_apply(const float* __restrict__ base, float* __restrict__ out_mem) {
    __shared__ int sidx[NB * TOPK];
    __shared__ float swp[NB];
    int tid = threadIdx.x;
    if (tid < NB * TOPK) sidx[tid] = g_topidx[tid];
    if (tid < NB) swp[tid] = g_wp[tid];
    __syncthreads();
    int p = blockIdx.x;
    int x = sidx[p];
    for (int p2 = p + 1; p2 < NB * TOPK; ++p2)
        if (sidx[p2] == x) return;     // a later batch rewrites this row
    float m = base[(size_t)x * DN + tid];
    for (int p2 = 0; p2 <= p; ++p2) {
        if (sidx[p2] == x) {
            float pw = swp[p2 >> 3];
            m = (1.0f - pw) * m + pw * g_qmean[(p2 >> 3) * DN + tid];
        }
    }
    out_mem[(size_t)x * DN + tid] = m;
}

// ---------------- launch ----------------
extern "C" void kernel_launch(void* const* d_in, const int* in_sizes, int n_in,
                              void* d_out, int out_size) {
    const float* query  = (const float*)d_in[0];
    const float* base   = (const float*)d_in[1];
    const float* loraA  = (const float*)d_in[2];
    const float* loraB  = (const float*)d_in[3];
    const float* w_ih   = (const float*)d_in[4];
    // d_in[5] = gru_w_hh: unused (h0 = 0 -> gh = b_hh exactly)
    const float* b_ih   = (const float*)d_in[6];
    const float* b_hh   = (const float*)d_in[7];
    const float* wg_w   = (const float*)d_in[8];
    const float* wg_b   = (const float*)d_in[9];

    float* out_retr   = (float*)d_out;                       // [32,8,512]
    float* out_hidden = out_retr + (size_t)NB * TOPK * DN;   // [32,512]
    float* out_mem    = out_hidden + (size_t)NB * DN;        // [131072,512]

    const int sc_smem = SC_SMEM_FLOATS * (int)sizeof(float); // 84 KB
    cudaFuncSetAttribute(k_scores, cudaFuncAttributeMaxDynamicSharedMemorySize, sc_smem);

    k_qmean<<<NB, DN>>>(query, loraB);
    k_scores<<<NBLK, 128, sc_smem>>>(base, loraA, out_mem);
    k_topk_merge<<<NB, 256>>>();
    k_retrieve<<<NB, DN>>>(base, loraA, loraB, out_retr);
    k_gx<<<3 * DN, 128>>>(w_ih, b_ih);
    k_hidden<<<NB, DN>>>(b_hh, wg_w, wg_b, out_hidden);
    k_apply<<<NB * TOPK, DN>>>(base, out_mem);
}